// round 2
// baseline (speedup 1.0000x reference)
#include <cuda_runtime.h>
#include <cuda_bf16.h>
#include <stdint.h>

#define Bn 64
#define Cn 128
#define Hn 56
#define Wn 56
#define HWn (Hn*Wn)

#define ROWS 4
#define TILE_N (ROWS*Wn)
#define ACT_ROWS (ROWS+2)
#define ACT_W (Wn+2)
#define ACT_PIX (ACT_ROWS*ACT_W)
#define ACT_STRIDE 272
#define W_STRIDE 272
#define WBUF_BYTES (128*W_STRIDE)
#define ACT_BYTES (ACT_PIX*ACT_STRIDE)
#define SMEM_BYTES (ACT_BYTES + 2*WBUF_BYTES)
#define STAGE_STRIDE 132

__device__ __align__(16) uint4 g_bits1[Bn*HWn];
__device__ __align__(16) uint4 g_bits2[Bn*HWn];
__device__ __align__(16) __nv_bfloat16 g_w1[9*128*128];
__device__ __align__(16) __nv_bfloat16 g_w2[9*128*128];

__device__ __forceinline__ uint32_t smem_u32(const void* p){
    return (uint32_t)__cvta_generic_to_shared(p);
}
__device__ __forceinline__ void ldsm4(uint32_t* r, uint32_t addr){
    asm volatile("ldmatrix.sync.aligned.m8n8.x4.shared.b16 {%0,%1,%2,%3},[%4];"
        : "=r"(r[0]),"=r"(r[1]),"=r"(r[2]),"=r"(r[3]) : "r"(addr));
}
__device__ __forceinline__ void ldsm2(uint32_t* r, uint32_t addr){
    asm volatile("ldmatrix.sync.aligned.m8n8.x2.shared.b16 {%0,%1},[%2];"
        : "=r"(r[0]),"=r"(r[1]) : "r"(addr));
}
__device__ __forceinline__ void mma16816(float* d, const uint32_t* a, const uint32_t* b){
    asm volatile("mma.sync.aligned.m16n8k16.row.col.f32.bf16.bf16.f32 "
        "{%0,%1,%2,%3},{%4,%5,%6,%7},{%8,%9},{%0,%1,%2,%3};"
        : "+f"(d[0]),"+f"(d[1]),"+f"(d[2]),"+f"(d[3])
        : "r"(a[0]),"r"(a[1]),"r"(a[2]),"r"(a[3]),"r"(b[0]),"r"(b[1]));
}
__device__ __forceinline__ void cpasync16(uint32_t s, const void* g){
    asm volatile("cp.async.cg.shared.global [%0],[%1],16;" :: "r"(s), "l"(g));
}
__device__ __forceinline__ void cpcommit(){ asm volatile("cp.async.commit_group;"); }
template<int N> __device__ __forceinline__ void cpwait(){
    asm volatile("cp.async.wait_group %0;" :: "n"(N));
}

__global__ void prep_w(const float* __restrict__ w1, const float* __restrict__ w2){
    int i = blockIdx.x*blockDim.x + threadIdx.x;
    if (i >= 9*128*128) return;
    int c = i & 127;
    int o = (i >> 7) & 127;
    int t = i >> 14;
    int row = t/3, col = t - row*3;
    int s = ((o*128 + c)*3 + row)*3 + col;
    float a = w1[s], b = w2[s];
    g_w1[i] = __float2bfloat16((a>0.f)?1.f:((a<0.f)?-1.f:0.f));
    g_w2[i] = __float2bfloat16((b>0.f)?1.f:((b<0.f)?-1.f:0.f));
}

__global__ void pack_x(const float* __restrict__ x){
    int p = blockIdx.x*blockDim.x + threadIdx.x;
    if (p >= Bn*HWn) return;
    int b  = p / HWn;
    int hw = p - b*HWn;
    const float* base = x + (size_t)b*Cn*HWn + hw;
    uint32_t w0=0,w1=0,w2=0,w3=0;
    #pragma unroll
    for (int c=0;c<32;c++)  w0 |= (base[(size_t)(c    )*HWn] < 0.f ? 1u:0u) << c;
    #pragma unroll
    for (int c=0;c<32;c++)  w1 |= (base[(size_t)(c+32 )*HWn] < 0.f ? 1u:0u) << c;
    #pragma unroll
    for (int c=0;c<32;c++)  w2 |= (base[(size_t)(c+64 )*HWn] < 0.f ? 1u:0u) << c;
    #pragma unroll
    for (int c=0;c<32;c++)  w3 |= (base[(size_t)(c+96 )*HWn] < 0.f ? 1u:0u) << c;
    g_bits1[p] = make_uint4(w0,w1,w2,w3);
}

template<int PASS>
__global__ void __launch_bounds__(256,1)
conv_bin(const float* __restrict__ gamma, const float* __restrict__ beta,
         const float* __restrict__ mean,  const float* __restrict__ var,
         const float* __restrict__ xres,  float* __restrict__ out)
{
    extern __shared__ char smem[];
    char* act = smem;
    char* wsm = smem + ACT_BYTES;

    const int tid  = threadIdx.x;
    const int lane = tid & 31;
    const int warp = tid >> 5;
    const int wm   = warp & 3;
    const int wn   = warp >> 2;
    const int b    = blockIdx.y;
    const int y0   = blockIdx.x * ROWS;

    const uint4* bits_in = (PASS==1) ? g_bits1 : g_bits2;
    const __nv_bfloat16* wg = (PASS==1) ? g_w1 : g_w2;

    // prefetch weight taps 0,1
    {
        const char* gsrc = (const char*)wg;
        uint32_t wb = smem_u32(wsm);
        #pragma unroll
        for (int i=0;i<8;i++){
            int e = i*256 + tid;
            cpasync16(wb + (e>>4)*W_STRIDE + (e&15)*16, gsrc + (size_t)e*16);
        }
        cpcommit();
        gsrc += 32768;
        #pragma unroll
        for (int i=0;i<8;i++){
            int e = i*256 + tid;
            cpasync16(wb + WBUF_BYTES + (e>>4)*W_STRIDE + (e&15)*16, gsrc + (size_t)e*16);
        }
        cpcommit();
    }

    // expand sign bits -> bf16 (+1/-1), pads=0
    for (int idx = tid; idx < ACT_PIX; idx += 256){
        int r  = idx / ACT_W;
        int xc = idx - r*ACT_W;
        int gy = y0 - 1 + r;
        int gx = xc - 1;
        uint4 bw = make_uint4(0,0,0,0);
        bool valid = ((unsigned)gy < (unsigned)Hn) && ((unsigned)gx < (unsigned)Wn);
        if (valid) bw = bits_in[(b*Hn + gy)*Wn + gx];
        uint32_t* dst = (uint32_t*)(act + (size_t)idx*ACT_STRIDE);
        uint32_t arr[4] = {bw.x, bw.y, bw.z, bw.w};
        #pragma unroll
        for (int g=0;g<4;g++){
            uint32_t bwv = arr[g];
            #pragma unroll
            for (int j=0;j<16;j++){
                uint32_t b2 = (bwv >> (2*j)) & 3u;
                uint32_t pr = valid ? (0x3F803F80u | ((b2&1u)<<15) | ((b2>>1)<<31)) : 0u;
                dst[g*16 + j] = pr;
            }
        }
    }

    const uint32_t act_base = smem_u32(act);
    const uint32_t w_base   = smem_u32(wsm);
    const uint32_t aoff = (uint32_t)(wm*32 + (lane&15))*W_STRIDE + (uint32_t)(lane>>4)*16;

    float acc[2][14][4];
    #pragma unroll
    for (int i=0;i<2;i++)
        #pragma unroll
        for (int j=0;j<14;j++)
            #pragma unroll
            for (int e=0;e<4;e++) acc[i][j][e] = 0.f;

    for (int t=0; t<9; ++t){
        cpwait<1>();
        __syncthreads();

        const int dy = t/3, dx = t - dy*3;
        const uint32_t wb = w_base + (uint32_t)(t&1)*WBUF_BYTES + aoff;

        uint32_t baddr[14];
        #pragma unroll
        for (int j=0;j<14;j++){
            int ryj = wn*2 + ((j>=7)?1:0);
            int xs  = (j - ((j>=7)?7:0))*8;
            int pix0 = (ryj + dy)*ACT_W + xs + dx;
            baddr[j] = act_base + (uint32_t)(pix0 + (lane&7))*ACT_STRIDE
                     + (uint32_t)((lane>>3)&1)*16;
        }

        #pragma unroll
        for (int ks=0; ks<8; ks++){
            uint32_t a0[4], a1[4];
            ldsm4(a0, wb + ks*32);
            ldsm4(a1, wb + 16*W_STRIDE + ks*32);
            uint32_t bf[14][2];
            #pragma unroll
            for (int j=0;j<14;j++) ldsm2(bf[j], baddr[j] + ks*32);
            #pragma unroll
            for (int j=0;j<14;j++){
                mma16816(acc[0][j], a0, bf[j]);
                mma16816(acc[1][j], a1, bf[j]);
            }
        }
        __syncthreads();

        if (t+2 < 9){
            const char* gsrc = (const char*)(wg + (size_t)(t+2)*16384);
            uint32_t sdst = w_base + (uint32_t)(t&1)*WBUF_BYTES;
            #pragma unroll
            for (int i=0;i<8;i++){
                int e = i*256 + tid;
                cpasync16(sdst + (e>>4)*W_STRIDE + (e&15)*16, gsrc + (size_t)e*16);
            }
        }
        cpcommit();
    }

    const int gr = lane >> 2;
    const int ct = lane & 3;
    float inv[4], bia[4];
    #pragma unroll
    for (int k=0;k<4;k++){
        int o = wm*32 + (k>>1)*16 + (k&1)*8 + gr;
        float iv = gamma[o] / sqrtf(var[o] + 1e-5f);
        inv[k] = iv;
        bia[k] = beta[o] - mean[o]*iv;
    }

    if (PASS == 2){
        #pragma unroll
        for (int mf=0; mf<2; mf++){
            #pragma unroll
            for (int j=0;j<14;j++){
                int ry = wn*2 + ((j>=7)?1:0);
                int xx = (j - ((j>=7)?7:0))*8 + ct*2;
                int y  = y0 + ry;
                #pragma unroll
                for (int h=0;h<2;h++){
                    int o = wm*32 + mf*16 + h*8 + gr;
                    int k = mf*2 + h;
                    size_t base = ((size_t)(b*Cn + o)*Hn + y)*Wn + xx;
                    #pragma unroll
                    for (int cc=0; cc<2; cc++){
                        float v = __fadd_rn(__fmul_rn(acc[mf][j][h*2+cc], inv[k]), bia[k]);
                        v += xres[base + cc];
                        v = fminf(fmaxf(v, -1.0f), 1.0f);
                        out[base + cc] = v;
                    }
                }
            }
        }
    } else {
        char* stage = wsm;
        #pragma unroll
        for (int mf=0; mf<2; mf++){
            #pragma unroll
            for (int j=0;j<14;j++){
                int nb = wn*112 + j*8 + ct*2;
                #pragma unroll
                for (int h=0;h<2;h++){
                    int o = wm*32 + mf*16 + h*8 + gr;
                    int k = mf*2 + h;
                    #pragma unroll
                    for (int cc=0; cc<2; cc++){
                        float v = __fadd_rn(__fmul_rn(acc[mf][j][h*2+cc], inv[k]), bia[k]);
                        stage[(size_t)(nb+cc)*STAGE_STRIDE + o] = (v < 0.f) ? (char)1 : (char)0;
                    }
                }
            }
        }
        __syncthreads();
        if (tid < TILE_N){
            int n  = tid;
            int ry = n / 56;
            int xx = n - ry*56;
            int y  = y0 + ry;
            const uint32_t* src = (const uint32_t*)(stage + (size_t)n*STAGE_STRIDE);
            uint32_t wd[4];
            #pragma unroll
            for (int g=0; g<4; g++){
                uint32_t wv = 0;
                #pragma unroll
                for (int i=0;i<8;i++){
                    unsigned nib = __dp4a(src[g*8 + i], 0x08040201u, 0u);
                    wv |= nib << (4*i);
                }
                wd[g] = wv;
            }
            g_bits2[(b*Hn + y)*Wn + xx] = make_uint4(wd[0],wd[1],wd[2],wd[3]);
        }
    }
}

extern "C" void kernel_launch(void* const* d_in, const int* in_sizes, int n_in,
                              void* d_out, int out_size)
{
    const float* x      = (const float*)d_in[0];
    const float* w1     = (const float*)d_in[1];
    const float* w2     = (const float*)d_in[2];
    const float* gamma1 = (const float*)d_in[3];
    const float* beta1  = (const float*)d_in[4];
    const float* mean1  = (const float*)d_in[5];
    const float* var1   = (const float*)d_in[6];
    const float* gamma2 = (const float*)d_in[7];
    const float* beta2  = (const float*)d_in[8];
    const float* mean2  = (const float*)d_in[9];
    const float* var2   = (const float*)d_in[10];
    float* out = (float*)d_out;

    cudaFuncSetAttribute(conv_bin<1>, cudaFuncAttributeMaxDynamicSharedMemorySize, SMEM_BYTES);
    cudaFuncSetAttribute(conv_bin<2>, cudaFuncAttributeMaxDynamicSharedMemorySize, SMEM_BYTES);

    prep_w<<<576, 256>>>(w1, w2);
    pack_x<<<784, 256>>>(x);

    dim3 grid(Hn/ROWS, Bn);
    conv_bin<1><<<grid, 256, SMEM_BYTES>>>(gamma1, beta1, mean1, var1, x, out);
    conv_bin<2><<<grid, 256, SMEM_BYTES>>>(gamma2, beta2, mean2, var2, x, out);
}

// round 3
// speedup vs baseline: 1.0108x; 1.0108x over previous
#include <cuda_runtime.h>
#include <cuda_bf16.h>
#include <stdint.h>

#define Bn 64
#define Cn 128
#define Hn 56
#define Wn 56
#define HWn (Hn*Wn)

#define ROWS 4
#define TILE_N (ROWS*Wn)
#define ACT_ROWS (ROWS+2)
#define ACT_W (Wn+2)
#define ACT_PIX (ACT_ROWS*ACT_W)
#define ACT_STRIDE 272
#define W_STRIDE 272
#define WBUF_BYTES (128*W_STRIDE)
#define ACT_BYTES (ACT_PIX*ACT_STRIDE)
#define NSTAGE 3
#define SMEM_BYTES (ACT_BYTES + NSTAGE*WBUF_BYTES)
#define STAGE_STRIDE 132

__device__ __align__(16) uint4 g_bits1[Bn*HWn];
__device__ __align__(16) uint4 g_bits2[Bn*HWn];
__device__ __align__(16) __nv_bfloat16 g_w1[9*128*128];
__device__ __align__(16) __nv_bfloat16 g_w2[9*128*128];

__device__ __forceinline__ uint32_t smem_u32(const void* p){
    return (uint32_t)__cvta_generic_to_shared(p);
}
__device__ __forceinline__ void ldsm4(uint32_t* r, uint32_t addr){
    asm volatile("ldmatrix.sync.aligned.m8n8.x4.shared.b16 {%0,%1,%2,%3},[%4];"
        : "=r"(r[0]),"=r"(r[1]),"=r"(r[2]),"=r"(r[3]) : "r"(addr));
}
__device__ __forceinline__ void mma16816(float* d, const uint32_t* a, const uint32_t* b){
    asm volatile("mma.sync.aligned.m16n8k16.row.col.f32.bf16.bf16.f32 "
        "{%0,%1,%2,%3},{%4,%5,%6,%7},{%8,%9},{%0,%1,%2,%3};"
        : "+f"(d[0]),"+f"(d[1]),"+f"(d[2]),"+f"(d[3])
        : "r"(a[0]),"r"(a[1]),"r"(a[2]),"r"(a[3]),"r"(b[0]),"r"(b[1]));
}
__device__ __forceinline__ void cpasync16(uint32_t s, const void* g){
    asm volatile("cp.async.cg.shared.global [%0],[%1],16;" :: "r"(s), "l"(g));
}
__device__ __forceinline__ void cpcommit(){ asm volatile("cp.async.commit_group;"); }
template<int N> __device__ __forceinline__ void cpwait(){
    asm volatile("cp.async.wait_group %0;" :: "n"(N));
}

__global__ void prep_w(const float* __restrict__ w1, const float* __restrict__ w2){
    int i = blockIdx.x*blockDim.x + threadIdx.x;
    if (i >= 9*128*128) return;
    int c = i & 127;
    int o = (i >> 7) & 127;
    int t = i >> 14;
    int row = t/3, col = t - row*3;
    int s = ((o*128 + c)*3 + row)*3 + col;
    float a = w1[s], b = w2[s];
    g_w1[i] = __float2bfloat16((a>0.f)?1.f:((a<0.f)?-1.f:0.f));
    g_w2[i] = __float2bfloat16((b>0.f)?1.f:((b<0.f)?-1.f:0.f));
}

__global__ void pack_x(const float* __restrict__ x){
    int p = blockIdx.x*blockDim.x + threadIdx.x;
    if (p >= Bn*HWn) return;
    int b  = p / HWn;
    int hw = p - b*HWn;
    const float* base = x + (size_t)b*Cn*HWn + hw;
    uint32_t w0=0,w1=0,w2=0,w3=0;
    #pragma unroll
    for (int c=0;c<32;c++)  w0 |= (base[(size_t)(c    )*HWn] < 0.f ? 1u:0u) << c;
    #pragma unroll
    for (int c=0;c<32;c++)  w1 |= (base[(size_t)(c+32 )*HWn] < 0.f ? 1u:0u) << c;
    #pragma unroll
    for (int c=0;c<32;c++)  w2 |= (base[(size_t)(c+64 )*HWn] < 0.f ? 1u:0u) << c;
    #pragma unroll
    for (int c=0;c<32;c++)  w3 |= (base[(size_t)(c+96 )*HWn] < 0.f ? 1u:0u) << c;
    g_bits1[p] = make_uint4(w0,w1,w2,w3);
}

template<int PASS>
__global__ void __launch_bounds__(256,1)
conv_bin(const float* __restrict__ gamma, const float* __restrict__ beta,
         const float* __restrict__ mean,  const float* __restrict__ var,
         const float* __restrict__ xres,  float* __restrict__ out)
{
    extern __shared__ char smem[];
    char* act = smem;
    char* wsm = smem + ACT_BYTES;

    const int tid  = threadIdx.x;
    const int lane = tid & 31;
    const int warp = tid >> 5;
    const int wm   = warp & 3;
    const int wn   = warp >> 2;
    const int b    = blockIdx.y;
    const int y0   = blockIdx.x * ROWS;

    const uint4* bits_in = (PASS==1) ? g_bits1 : g_bits2;
    const __nv_bfloat16* wg = (PASS==1) ? g_w1 : g_w2;

    // prefetch weight taps 0,1 into stage buffers 0,1
    {
        const char* gsrc = (const char*)wg;
        uint32_t wb = smem_u32(wsm);
        #pragma unroll
        for (int i=0;i<8;i++){
            int e = i*256 + tid;
            cpasync16(wb + (e>>4)*W_STRIDE + (e&15)*16, gsrc + (size_t)e*16);
        }
        cpcommit();
        gsrc += 32768;
        #pragma unroll
        for (int i=0;i<8;i++){
            int e = i*256 + tid;
            cpasync16(wb + WBUF_BYTES + (e>>4)*W_STRIDE + (e&15)*16, gsrc + (size_t)e*16);
        }
        cpcommit();
    }

    // expand sign bits -> bf16 (+1/-1), pads=0 (overlaps with cp.async above)
    for (int idx = tid; idx < ACT_PIX; idx += 256){
        int r  = idx / ACT_W;
        int xc = idx - r*ACT_W;
        int gy = y0 - 1 + r;
        int gx = xc - 1;
        uint4 bw = make_uint4(0,0,0,0);
        bool valid = ((unsigned)gy < (unsigned)Hn) && ((unsigned)gx < (unsigned)Wn);
        if (valid) bw = bits_in[(b*Hn + gy)*Wn + gx];
        uint32_t* dst = (uint32_t*)(act + (size_t)idx*ACT_STRIDE);
        uint32_t arr[4] = {bw.x, bw.y, bw.z, bw.w};
        #pragma unroll
        for (int g=0;g<4;g++){
            uint32_t bwv = arr[g];
            #pragma unroll
            for (int j=0;j<16;j++){
                uint32_t b2 = (bwv >> (2*j)) & 3u;
                uint32_t pr = valid ? (0x3F803F80u | ((b2&1u)<<15) | ((b2>>1)<<31)) : 0u;
                dst[g*16 + j] = pr;
            }
        }
    }

    const uint32_t act_base = smem_u32(act);
    const uint32_t w_base   = smem_u32(wsm);
    const uint32_t aoff = (uint32_t)(wm*32 + (lane&15))*W_STRIDE + (uint32_t)(lane>>4)*16;

    float acc[2][14][4];
    #pragma unroll
    for (int i=0;i<2;i++)
        #pragma unroll
        for (int j=0;j<14;j++)
            #pragma unroll
            for (int e=0;e<4;e++) acc[i][j][e] = 0.f;

    // precompute per-lane B fragment selector (pairs of n-frags per ldsm4)
    const int bsel = (lane >> 4) & 1;       // 0 -> frag 2m, 1 -> frag 2m+1
    const int brow = lane & 7;              // pixel within 8-group
    const int bk16 = (lane >> 3) & 1;       // k-half -> +16B

    for (int t=0; t<9; ++t){
        cpwait<1>();
        __syncthreads();       // tap t weights visible to all; also proves tap t-1 reads done

        // issue tap t+2 into buffer (t+2)%3 BEFORE compute (overlap DMA with MMA)
        if (t+2 < 9){
            const char* gsrc = (const char*)(wg + (size_t)(t+2)*16384);
            uint32_t sdst = w_base + (uint32_t)((t+2)%NSTAGE)*WBUF_BYTES;
            #pragma unroll
            for (int i=0;i<8;i++){
                int e = i*256 + tid;
                cpasync16(sdst + (e>>4)*W_STRIDE + (e&15)*16, gsrc + (size_t)e*16);
            }
        }
        cpcommit();

        const int dy = t/3, dx = t - dy*3;
        const uint32_t wb = w_base + (uint32_t)(t%NSTAGE)*WBUF_BYTES + aoff;

        // B addresses: 7 ldsm4, each loading n-frags {2m, 2m+1} x 2 k-halves
        uint32_t baddr[7];
        #pragma unroll
        for (int m=0;m<7;m++){
            int jA = 2*m, jB = 2*m+1;
            int j  = bsel ? jB : jA;
            int ryj = wn*2 + ((j>=7)?1:0);
            int xs  = (j - ((j>=7)?7:0))*8;
            int pix0 = (ryj + dy)*ACT_W + xs + dx;
            baddr[m] = act_base + (uint32_t)(pix0 + brow)*ACT_STRIDE
                     + (uint32_t)bk16*16;
        }

        #pragma unroll
        for (int ks=0; ks<8; ks++){
            uint32_t a0[4], a1[4];
            ldsm4(a0, wb + ks*32);
            ldsm4(a1, wb + 16*W_STRIDE + ks*32);
            uint32_t bf[7][4];
            #pragma unroll
            for (int m=0;m<7;m++) ldsm4(bf[m], baddr[m] + ks*32);
            #pragma unroll
            for (int m=0;m<7;m++){
                mma16816(acc[0][2*m  ], a0, &bf[m][0]);
                mma16816(acc[0][2*m+1], a0, &bf[m][2]);
                mma16816(acc[1][2*m  ], a1, &bf[m][0]);
                mma16816(acc[1][2*m+1], a1, &bf[m][2]);
            }
        }
    }

    const int gr = lane >> 2;
    const int ct = lane & 3;
    float inv[4], bia[4];
    #pragma unroll
    for (int k=0;k<4;k++){
        int o = wm*32 + (k>>1)*16 + (k&1)*8 + gr;
        float iv = gamma[o] / sqrtf(var[o] + 1e-5f);
        inv[k] = iv;
        bia[k] = beta[o] - mean[o]*iv;
    }

    if (PASS == 2){
        #pragma unroll
        for (int mf=0; mf<2; mf++){
            #pragma unroll
            for (int j=0;j<14;j++){
                int ry = wn*2 + ((j>=7)?1:0);
                int xx = (j - ((j>=7)?7:0))*8 + ct*2;
                int y  = y0 + ry;
                #pragma unroll
                for (int h=0;h<2;h++){
                    int o = wm*32 + mf*16 + h*8 + gr;
                    int k = mf*2 + h;
                    size_t base = ((size_t)(b*Cn + o)*Hn + y)*Wn + xx;
                    #pragma unroll
                    for (int cc=0; cc<2; cc++){
                        float v = __fadd_rn(__fmul_rn(acc[mf][j][h*2+cc], inv[k]), bia[k]);
                        v += xres[base + cc];
                        v = fminf(fmaxf(v, -1.0f), 1.0f);
                        out[base + cc] = v;
                    }
                }
            }
        }
    } else {
        char* stage = wsm;   // weights no longer needed
        __syncthreads();     // all warps done reading weight buffers before overwrite
        #pragma unroll
        for (int mf=0; mf<2; mf++){
            #pragma unroll
            for (int j=0;j<14;j++){
                int nb = wn*112 + j*8 + ct*2;
                #pragma unroll
                for (int h=0;h<2;h++){
                    int o = wm*32 + mf*16 + h*8 + gr;
                    int k = mf*2 + h;
                    #pragma unroll
                    for (int cc=0; cc<2; cc++){
                        float v = __fadd_rn(__fmul_rn(acc[mf][j][h*2+cc], inv[k]), bia[k]);
                        stage[(size_t)(nb+cc)*STAGE_STRIDE + o] = (v < 0.f) ? (char)1 : (char)0;
                    }
                }
            }
        }
        __syncthreads();
        if (tid < TILE_N){
            int n  = tid;
            int ry = n / 56;
            int xx = n - ry*56;
            int y  = y0 + ry;
            const uint32_t* src = (const uint32_t*)(stage + (size_t)n*STAGE_STRIDE);
            uint32_t wd[4];
            #pragma unroll
            for (int g=0; g<4; g++){
                uint32_t wv = 0;
                #pragma unroll
                for (int i=0;i<8;i++){
                    unsigned nib = __dp4a(src[g*8 + i], 0x08040201u, 0u);
                    wv |= nib << (4*i);
                }
                wd[g] = wv;
            }
            g_bits2[(b*Hn + y)*Wn + xx] = make_uint4(wd[0],wd[1],wd[2],wd[3]);
        }
    }
}

extern "C" void kernel_launch(void* const* d_in, const int* in_sizes, int n_in,
                              void* d_out, int out_size)
{
    const float* x      = (const float*)d_in[0];
    const float* w1     = (const float*)d_in[1];
    const float* w2     = (const float*)d_in[2];
    const float* gamma1 = (const float*)d_in[3];
    const float* beta1  = (const float*)d_in[4];
    const float* mean1  = (const float*)d_in[5];
    const float* var1   = (const float*)d_in[6];
    const float* gamma2 = (const float*)d_in[7];
    const float* beta2  = (const float*)d_in[8];
    const float* mean2  = (const float*)d_in[9];
    const float* var2   = (const float*)d_in[10];
    float* out = (float*)d_out;

    cudaFuncSetAttribute(conv_bin<1>, cudaFuncAttributeMaxDynamicSharedMemorySize, SMEM_BYTES);
    cudaFuncSetAttribute(conv_bin<2>, cudaFuncAttributeMaxDynamicSharedMemorySize, SMEM_BYTES);

    prep_w<<<576, 256>>>(w1, w2);
    pack_x<<<784, 256>>>(x);

    dim3 grid(Hn/ROWS, Bn);
    conv_bin<1><<<grid, 256, SMEM_BYTES>>>(gamma1, beta1, mean1, var1, x, out);
    conv_bin<2><<<grid, 256, SMEM_BYTES>>>(gamma2, beta2, mean2, var2, x, out);
}